// round 3
// baseline (speedup 1.0000x reference)
#include <cuda_runtime.h>

// TCLWithoutParametersLoss: B=65536, D=512, C=21
//   e_j = 0.5*||c_j||^2 - f.c_j      (0.5||f||^2 cancels in pos-neg)
//   loss = mean( relu(e_label + 5 - min_{j!=label} e_j) )
//
// Design:
//  - grid = 148 persistent blocks (1/SM), 512 threads; block owns 442/443 rows
//  - all 21 centers in SMEM (43KB); features double-buffer staged through SMEM
//    in 16-float k-stages with coalesced global loads
//  - dot products via packed fma.rn.f32x2 (FFMA2) -> 2 MACs per fma-pipe slot
//  - labels dtype is runtime-detected (JAX x64-off silently makes int64->int32):
//    if the first 512 odd 32-bit words are all zero it is int64 (stride-2 read),
//    otherwise int32 (stride-1). Only bytes valid under BOTH layouts are probed.
//  - block reduce + atomicAdd(double) to __device__ scratch; last block writes
//    the mean and resets state (graph-replay deterministic)

#define NB      148
#define NT      512
#define BATCH   65536
#define DIMS    512
#define NC      21
#define MARGINF 5.0f

#define STAGES   32            // 16 floats per k-stage
#define ROWS_MAX 448
#define FSTRIDE  5             // float4 units per staged row (4 data + 1 pad)

__device__ double       g_sum_d  = 0.0;
__device__ unsigned int g_done_d = 0u;

__device__ __forceinline__ unsigned long long ffma2(unsigned long long a,
                                                    unsigned long long b,
                                                    unsigned long long c) {
    unsigned long long r;
    asm("fma.rn.f32x2 %0, %1, %2, %3;" : "=l"(r) : "l"(a), "l"(b), "l"(c));
    return r;
}

extern __shared__ float4 smem4[];
// dynamic smem layout (float4 units):
//   [0, 2688)                      centers  (21*512 floats = 43008 B)
//   [2688, 2688+2240)              stage buf 0 (448 rows * 5 float4)
//   [2688+2240, 2688+4480)         stage buf 1
// total = 7168 float4 = 114688 B

__global__ void __launch_bounds__(NT, 1)
tcl_kernel(const float* __restrict__ features,
           const float* __restrict__ centers,
           const int*   __restrict__ labels32,   // raw words; stride decided at runtime
           float* __restrict__ out)
{
    float4* s_c4  = smem4;
    float4* s_b0  = smem4 + 2688;
    float4* s_b1  = smem4 + 2688 + ROWS_MAX * FSTRIDE;

    __shared__ float s_hc2[NC];
    __shared__ float s_red[NT / 32];
    __shared__ int   s_is32;

    const int tid = threadIdx.x;
    const int bid = blockIdx.x;

    if (tid == 0) s_is32 = 0;

    // ---- load centers into SMEM (2688 float4) ----
    const float4* c4 = (const float4*)centers;
    for (int i = tid; i < NC * DIMS / 4; i += NT) s_c4[i] = c4[i];
    __syncthreads();   // also orders s_is32 init

    // ---- labels dtype probe: odd words 1,3,...,1023 (valid in both layouts).
    // int64 data (values in [0,21)) => all-zero odd words; int32 => ~random labels.
    if (labels32[2 * tid + 1] != 0) s_is32 = 1;   // benign write race

    // ---- 0.5*||c_j||^2 : 16 lanes per center, warp-local width-16 reduce ----
    if (tid < 352) {                       // 22*16, full warps active for shfl
        int j = tid >> 4, l = tid & 15;
        float s = 0.f;
        if (j < NC) {
            const float* cj = (const float*)s_c4 + j * DIMS;
            #pragma unroll 4
            for (int k = l; k < DIMS; k += 16) { float v = cj[k]; s += v * v; }
        }
        #pragma unroll
        for (int off = 8; off; off >>= 1)
            s += __shfl_down_sync(0xffffffffu, s, off, 16);
        if (j < NC && l == 0) s_hc2[j] = 0.5f * s;
    }

    // ---- row range for this block: exact balance 442/443 rows per SM ----
    const int base = bid * 442 + min(bid, 120);
    const int cnt  = 442 + (bid < 120 ? 1 : 0);

    const float4* f4 = (const float4*)features;

    unsigned long long acc[NC];
    #pragma unroll
    for (int j = 0; j < NC; j++) acc[j] = 0ull;   // packed (0.f, 0.f)

    // prologue: stage 0 into buf0 (coalesced)
    {
        const int n = cnt * 4;
        for (int idx = tid; idx < n; idx += NT) {
            int row = idx >> 2, q = idx & 3;
            s_b0[row * FSTRIDE + q] = f4[(size_t)(base + row) * 128 + q];
        }
    }

    for (int s = 0; s < STAGES; s++) {
        __syncthreads();
        // kick next stage's coalesced loads into the other buffer
        if (s + 1 < STAGES) {
            const int n = cnt * 4;
            const int koff = (s + 1) * 4;
            float4* dst = ((s + 1) & 1) ? s_b1 : s_b0;
            for (int idx = tid; idx < n; idx += NT) {
                int row = idx >> 2, q = idx & 3;
                dst[row * FSTRIDE + q] = f4[(size_t)(base + row) * 128 + koff + q];
            }
        }
        // compute on current stage: 16 floats x 21 centers, packed f32x2 FMA
        if (tid < cnt) {
            const float4* cur = (s & 1) ? s_b1 : s_b0;
            const ulonglong2* fb = (const ulonglong2*)(cur + tid * FSTRIDE);
            ulonglong2 fv0 = fb[0], fv1 = fb[1], fv2 = fb[2], fv3 = fb[3];
            const ulonglong2* cb = (const ulonglong2*)s_c4 + s * 4;
            #pragma unroll
            for (int j = 0; j < NC; j++) {
                const ulonglong2* cj = cb + j * 128;   // 128 float4 per center
                ulonglong2 cv0 = cj[0], cv1 = cj[1], cv2 = cj[2], cv3 = cj[3];
                unsigned long long a = acc[j];
                a = ffma2(fv0.x, cv0.x, a);
                a = ffma2(fv0.y, cv0.y, a);
                a = ffma2(fv1.x, cv1.x, a);
                a = ffma2(fv1.y, cv1.y, a);
                a = ffma2(fv2.x, cv2.x, a);
                a = ffma2(fv2.y, cv2.y, a);
                a = ffma2(fv3.x, cv3.x, a);
                a = ffma2(fv3.y, cv3.y, a);
                acc[j] = a;
            }
        }
    }

    // ---- epilogue: e_j, pos/neg, hinge ----
    float myloss = 0.f;
    if (tid < cnt) {
        int r   = base + tid;
        int lab = s_is32 ? labels32[r] : labels32[2 * r];   // int32 vs int64 low word
        float pos = 0.f;
        float neg = 3.402823466e38f;
        #pragma unroll
        for (int j = 0; j < NC; j++) {
            float lo  = __uint_as_float((unsigned)(acc[j] & 0xffffffffull));
            float hi  = __uint_as_float((unsigned)(acc[j] >> 32));
            float dot = lo + hi;
            float e   = s_hc2[j] - dot;
            if (j == lab) pos = e;
            else          neg = fminf(neg, e);
        }
        myloss = fmaxf(pos + MARGINF - neg, 0.f);
    }

    // ---- block reduction ----
    #pragma unroll
    for (int off = 16; off; off >>= 1)
        myloss += __shfl_down_sync(0xffffffffu, myloss, off);
    if ((tid & 31) == 0) s_red[tid >> 5] = myloss;
    __syncthreads();
    if (tid < 32) {
        float v = (tid < NT / 32) ? s_red[tid] : 0.f;
        #pragma unroll
        for (int off = 8; off; off >>= 1)
            v += __shfl_down_sync(0xffffffffu, v, off);
        if (tid == 0) {
            atomicAdd(&g_sum_d, (double)v);
            __threadfence();
            unsigned p = atomicAdd(&g_done_d, 1u);
            if (p == NB - 1) {                 // last block finalizes
                __threadfence();
                double total = atomicAdd(&g_sum_d, 0.0);  // ordered read via L2
                *out = (float)(total * (1.0 / (double)BATCH));
                // reset scratch for next graph replay (ordered after *out use)
                g_sum_d = 0.0;
                __threadfence();
                g_done_d = 0u;
            }
        }
    }
}

extern "C" void kernel_launch(void* const* d_in, const int* in_sizes, int n_in,
                              void* d_out, int out_size) {
    const float* features = (const float*)d_in[0];
    const float* centers  = (const float*)d_in[1];
    const int*   labels   = (const int*)d_in[2];

    size_t shmem = (size_t)(2688 + 2 * ROWS_MAX * FSTRIDE) * sizeof(float4); // 114688 B
    cudaFuncSetAttribute(tcl_kernel,
                         cudaFuncAttributeMaxDynamicSharedMemorySize, (int)shmem);
    tcl_kernel<<<NB, NT, shmem>>>(features, centers, labels, (float*)d_out);
}